// round 2
// baseline (speedup 1.0000x reference)
#include <cuda_runtime.h>
#include <cstdint>

// PointPillarsBEV: PFN (linear+ReLU+max over 32 pts) -> scatter-add into (B,C,512,512).
// B=4, P=12000, NPTS=32, D=10, C=64, H=W=512. Output 268 MB fp32.
//
// Roofline model: the dense zero-fill of the output dominates (268 MB ~ 41 us at
// ~6.5 TB/s). Compute is ~2 GFLOP (negligible). Atomics (3.07M fp32, spread
// addresses) must land in L2: zero batch b's 64 MB slice (fits 126 MB L2), then
// immediately scatter batch b so the REDG atomics hit resident lines.

#define BEV_H 512
#define BEV_W 512
#define NPILLARS 12000
#define NPTS 32
#define DIN 10
#define CCH 64
#define HW (BEV_H * BEV_W)
#define PILLARS_PER_BLK 4

__global__ void zero_kernel(float4* __restrict__ dst) {
    // grid exactly covers one batch slice: 64*512*512 floats = 4,194,304 float4
    size_t i = (size_t)blockIdx.x * blockDim.x + threadIdx.x;
    dst[i] = make_float4(0.f, 0.f, 0.f, 0.f);
}

__global__ __launch_bounds__(PILLARS_PER_BLK * CCH) void pillar_scatter_kernel(
    const float* __restrict__ pillars,      // (B, P, 32, 10)
    const int*   __restrict__ coords,       // (B, P, 2)  (y, x)
    const float* __restrict__ w,            // (10, 64)
    const float* __restrict__ bias,         // (64,)
    float*       __restrict__ out,          // (B, 64, 512, 512)
    int batch)
{
    const int sub = threadIdx.x / CCH;                    // 0..3: pillar within block
    const int c   = threadIdx.x % CCH;                    // channel 0..63
    const int p   = blockIdx.x * PILLARS_PER_BLK + sub;   // pillar id (<= 12000, exact)

    __shared__ float pts[PILLARS_PER_BLK][NPTS * DIN];    // 4 * 320 floats

    const float* src = pillars + ((size_t)batch * NPILLARS + p) * (NPTS * DIN);
    #pragma unroll
    for (int i = c; i < NPTS * DIN; i += CCH)
        pts[sub][i] = src[i];

    float wc[DIN];
    #pragma unroll
    for (int d = 0; d < DIN; d++)
        wc[d] = w[d * CCH + c];          // coalesced across the 64 channel threads
    const float bc = bias[c];

    __syncthreads();

    // max over points of relu(dot + b); relu outputs >= 0 so m=0 init is exact
    // (matches reference: max over axis then relu-clamped at 0).
    float m = 0.f;
    #pragma unroll
    for (int n = 0; n < NPTS; n++) {
        float s = bc;
        #pragma unroll
        for (int d = 0; d < DIN; d++)
            s = fmaf(pts[sub][n * DIN + d], wc[d], s);
        m = fmaxf(m, s);
    }

    const int y = coords[((size_t)batch * NPILLARS + p) * 2 + 0];
    const int x = coords[((size_t)batch * NPILLARS + p) * 2 + 1];
    const int idx = y * BEV_W + x;

    // (B, C, H, W); no return value -> fire-and-forget REDG, serviced in L2
    atomicAdd(out + ((size_t)(batch * CCH + c)) * HW + idx, m);
}

extern "C" void kernel_launch(void* const* d_in, const int* in_sizes, int n_in,
                              void* d_out, int out_size) {
    const float* pillars = (const float*)d_in[0];
    const int*   coords  = (const int*)d_in[1];
    const float* pfn_w   = (const float*)d_in[2];
    const float* pfn_b   = (const float*)d_in[3];
    float* out = (float*)d_out;

    const size_t batch_floats = (size_t)CCH * HW;               // 16,777,216
    const int zero_threads = 256;
    const int zero_blocks  = (int)(batch_floats / 4 / zero_threads); // 16384

    // Interleave zero(b) + scatter(b) so each 64 MB slice is L2-resident
    // when its atomics arrive.
    for (int b = 0; b < 4; b++) {
        zero_kernel<<<zero_blocks, zero_threads>>>(
            (float4*)(out + (size_t)b * batch_floats));
        pillar_scatter_kernel<<<NPILLARS / PILLARS_PER_BLK, PILLARS_PER_BLK * CCH>>>(
            pillars, coords, pfn_w, pfn_b, out, b);
    }
}

// round 3
// speedup vs baseline: 1.1010x; 1.1010x over previous
#include <cuda_runtime.h>
#include <cstdint>

// PointPillarsBEV: PFN (linear+ReLU+max over 32 pts) -> scatter-add into (B,C,512,512).
// B=4, P=12000, NPTS=32, D=10, C=64. Output 268 MB fp32.
//
// R2 profile: scatter kernel (PFN fused w/ atomics) was issue/L1-bound at 25us/batch,
// zeroing ~9.5us/batch; kernels serialized -> 135us.
// R3: (a) fuse PFN into the zero kernel (compute blocks + zero blocks in one grid)
// so FMA hides under the DRAM-bound zero-fill; PFN writes to __device__ scratch.
// (b) f32x2 packed FMA over point-pairs + LDS.64 from dim-major shared: ~2x fewer
// issue slots. (c) scatter becomes a tiny atomic-only kernel into L2-resident lines.

#define BEV_H 512
#define BEV_W 512
#define NPILLARS 12000
#define NPTS 32
#define DIN 10
#define CCH 64
#define HW (BEV_H * BEV_W)            // 262144 = 1<<18

#define PILLARS_PER_CBLK 8            // 8 warps/block, 1 warp per pillar
#define NCOMP (NPILLARS / PILLARS_PER_CBLK)   // 1500 compute blocks
#define NZERO 4096                    // zero blocks: 4096*256 threads * 4 float4 = 64 MB
#define FUSED_GRID (NCOMP + NZERO)

__device__ float g_feats[4 * NPILLARS * CCH];   // 12.3 MB scratch (allowed: static __device__)

// ---- packed fp32x2 helpers (Blackwell; exact IEEE per lane) ----
__device__ __forceinline__ unsigned long long pack2(float lo, float hi) {
    unsigned long long r;
    asm("mov.b64 %0, {%1, %2};" : "=l"(r) : "f"(lo), "f"(hi));
    return r;
}
__device__ __forceinline__ void unpack2(unsigned long long v, float& lo, float& hi) {
    asm("mov.b64 {%0, %1}, %2;" : "=f"(lo), "=f"(hi) : "l"(v));
}
__device__ __forceinline__ unsigned long long fma2(unsigned long long a,
                                                   unsigned long long b,
                                                   unsigned long long c) {
    unsigned long long d;
    asm("fma.rn.f32x2 %0, %1, %2, %3;" : "=l"(d) : "l"(a), "l"(b), "l"(c));
    return d;
}

__global__ __launch_bounds__(256) void fused_zero_pfn_kernel(
    const float* __restrict__ pillars,   // (B, P, 32, 10)
    const float* __restrict__ w,         // (10, 64)
    const float* __restrict__ bias,      // (64,)
    float*       __restrict__ out,       // (B, 64, 512, 512)
    int batch)
{
    if (blockIdx.x < NCOMP) {
        // ---------------- PFN compute: 1 warp per pillar ----------------
        const int warp = threadIdx.x >> 5;
        const int lane = threadIdx.x & 31;
        const int p = blockIdx.x * PILLARS_PER_CBLK + warp;

        // dim-major staging: s_pts[warp][d][n] so a point-pair at dim d is 8B contiguous
        __shared__ float s_pts[PILLARS_PER_CBLK][DIN][NPTS];

        // lane = point index; 5 x LDG.64 (point base is 40B -> 8B aligned)
        const float* src = pillars + ((size_t)(batch * NPILLARS + p) * NPTS + lane) * DIN;
        const float2* src2 = (const float2*)src;
        float v[DIN];
        #pragma unroll
        for (int i = 0; i < 5; i++) {
            float2 t = src2[i];
            v[2 * i] = t.x;
            v[2 * i + 1] = t.y;
        }
        #pragma unroll
        for (int d = 0; d < DIN; d++)
            s_pts[warp][d][lane] = v[d];
        __syncwarp();

        // lane handles channels (lane, lane+32); weights duplicated into both halves
        unsigned long long wA[DIN], wB[DIN];
        #pragma unroll
        for (int d = 0; d < DIN; d++) {
            float wa = w[d * CCH + lane];
            float wb = w[d * CCH + lane + 32];
            wA[d] = pack2(wa, wa);
            wB[d] = pack2(wb, wb);
        }
        const float ba = bias[lane], bb = bias[lane + 32];
        const unsigned long long biasA = pack2(ba, ba);
        const unsigned long long biasB = pack2(bb, bb);

        float mA = 0.f, mB = 0.f;     // relu(...) >= 0, so 0-init is exact
        #pragma unroll
        for (int pr = 0; pr < NPTS / 2; pr++) {
            unsigned long long x2[DIN];
            #pragma unroll
            for (int d = 0; d < DIN; d++)   // broadcast LDS.64: points (2pr, 2pr+1) at dim d
                x2[d] = *reinterpret_cast<const unsigned long long*>(&s_pts[warp][d][2 * pr]);
            unsigned long long sA = biasA, sB = biasB;
            #pragma unroll
            for (int d = 0; d < DIN; d++) {
                sA = fma2(x2[d], wA[d], sA);
                sB = fma2(x2[d], wB[d], sB);
            }
            float lo, hi;
            unpack2(sA, lo, hi);
            mA = fmaxf(mA, fmaxf(lo, hi));
            unpack2(sB, lo, hi);
            mB = fmaxf(mB, fmaxf(lo, hi));
        }

        float* fp = g_feats + (size_t)(batch * NPILLARS + p) * CCH;
        fp[lane] = mA;
        fp[lane + 32] = mB;
    } else {
        // ---------------- zero-fill this batch's 64 MB canvas slice ----------------
        const int zb = blockIdx.x - NCOMP;
        float4* dst = (float4*)(out + (size_t)batch * CCH * HW);
        size_t base = (size_t)zb * 256 + threadIdx.x;
        const float4 z = make_float4(0.f, 0.f, 0.f, 0.f);
        #pragma unroll
        for (int k = 0; k < 4; k++)
            dst[base + (size_t)k * NZERO * 256] = z;   // covers 4,194,304 float4 exactly
    }
}

__global__ __launch_bounds__(256) void scatter_kernel(
    const int* __restrict__ coords,      // (B, P, 2)
    float*     __restrict__ out,         // (B, 64, 512, 512)
    int batch)
{
    const int t = blockIdx.x * 256 + threadIdx.x;    // [0, 12000*64)
    const int p = t >> 6;
    const int c = t & 63;

    const float f = g_feats[(size_t)(batch * NPILLARS + p) * CCH + c];
    const int y = __ldg(&coords[(size_t)(batch * NPILLARS + p) * 2 + 0]);
    const int x = __ldg(&coords[(size_t)(batch * NPILLARS + p) * 2 + 1]);

    // L2-resident lines (just zeroed); no return value -> REDG
    atomicAdd(out + ((size_t)(batch * CCH + c) << 18) + y * BEV_W + x, f);
}

extern "C" void kernel_launch(void* const* d_in, const int* in_sizes, int n_in,
                              void* d_out, int out_size) {
    const float* pillars = (const float*)d_in[0];
    const int*   coords  = (const int*)d_in[1];
    const float* pfn_w   = (const float*)d_in[2];
    const float* pfn_b   = (const float*)d_in[3];
    float* out = (float*)d_out;

    for (int b = 0; b < 4; b++) {
        fused_zero_pfn_kernel<<<FUSED_GRID, 256>>>(pillars, pfn_w, pfn_b, out, b);
        scatter_kernel<<<NPILLARS * CCH / 256, 256>>>(coords, out, b);
    }
}

// round 4
// speedup vs baseline: 1.1797x; 1.0714x over previous
#include <cuda_runtime.h>
#include <cstdint>

// PointPillarsBEV R4: touch the 268MB output exactly ONCE.
//   acc[b][cell][64] compact staging (cell-major -> coalesced 256B atomic bursts,
//   L2-resident), flag[b][cell] marks touched cells.
//   Pipeline: prep(zero flags + zero touched acc) ; pfn(b0) ;
//             {expand(b-1) + pfn(b)} x3 ; expand(b3).
//   Expand = single dense store pass (DRAM roofline ~42us); PFN (~26us FFMA floor)
//   hides under it via block specialization.

#define BEV_W 512
#define NPILLARS 12000
#define NPTS 32
#define DIN 10
#define CCH 64
#define HW 262144                    // 512*512 = 1<<18
#define PPB 8                        // pillars per 256-thread block (1 warp each)
#define NPFN (NPILLARS / PPB)        // 1500 pfn blocks per batch
#define NEXP 4096                    // expand blocks per batch (256 thr, 4 float4 each)

__device__ float g_acc[(size_t)4 * HW * CCH];          // 268MB staging (touched lines only)
__device__ unsigned char g_flag[4 * HW];               // 1MB

// ---- packed fp32x2 (exact IEEE per lane) ----
__device__ __forceinline__ uint64_t pack2(float lo, float hi) {
    uint64_t r; asm("mov.b64 %0, {%1, %2};" : "=l"(r) : "f"(lo), "f"(hi)); return r;
}
__device__ __forceinline__ void unpack2(uint64_t v, float& lo, float& hi) {
    asm("mov.b64 {%0, %1}, %2;" : "=f"(lo), "=f"(hi) : "l"(v));
}
__device__ __forceinline__ uint64_t fma2(uint64_t a, uint64_t b, uint64_t c) {
    uint64_t d; asm("fma.rn.f32x2 %0, %1, %2, %3;" : "=l"(d) : "l"(a), "l"(b), "l"(c)); return d;
}

// ---------------- prep: zero flags + zero touched acc cells ----------------
__global__ __launch_bounds__(256) void prep_kernel(const int* __restrict__ coords) {
    if (blockIdx.x < 256) {
        // zero 1MB of flags: 256 blk * 256 thr * 16B
        ((uint4*)g_flag)[blockIdx.x * 256 + threadIdx.x] = make_uint4(0, 0, 0, 0);
    } else {
        // one warp per pillar: zero its cell's 64 channels (benign races on collision)
        const int warp = threadIdx.x >> 5, lane = threadIdx.x & 31;
        const int pidx = (blockIdx.x - 256) * PPB + warp;      // [0, 48000)
        const int b = pidx / NPILLARS, p = pidx - b * NPILLARS;
        const int y = __ldg(&coords[(size_t)pidx * 2 + 0]);
        const int x = __ldg(&coords[(size_t)pidx * 2 + 1]);
        const size_t base = ((size_t)(b * HW) + y * BEV_W + x) * CCH;
        ((float2*)(g_acc + base))[lane] = make_float2(0.f, 0.f);
        (void)p;
    }
}

// ---------------- pfn+scatter for one pillar-warp ----------------
__device__ __forceinline__ void do_pfn(
    const float* __restrict__ pillars, const int* __restrict__ coords,
    const float* __restrict__ w, const float* __restrict__ bias,
    int batch, int pfnBlk)
{
    const int warp = threadIdx.x >> 5, lane = threadIdx.x & 31;
    const int p = pfnBlk * PPB + warp;

    __shared__ __align__(16) float s_pts[PPB][DIN][NPTS];   // dim-major

    // lane = point; 5x LDG.64 (40B point, 8B aligned)
    const float2* src2 = (const float2*)(pillars +
        ((size_t)(batch * NPILLARS + p) * NPTS + lane) * DIN);
    float v[DIN];
    #pragma unroll
    for (int i = 0; i < 5; i++) { float2 t = src2[i]; v[2*i] = t.x; v[2*i+1] = t.y; }
    #pragma unroll
    for (int d = 0; d < DIN; d++) s_pts[warp][d][lane] = v[d];
    __syncwarp();

    uint64_t wA[DIN], wB[DIN];
    #pragma unroll
    for (int d = 0; d < DIN; d++) {
        float wa = w[d * CCH + lane], wb = w[d * CCH + lane + 32];
        wA[d] = pack2(wa, wa); wB[d] = pack2(wb, wb);
    }
    const float ba = bias[lane], bb = bias[lane + 32];
    const uint64_t biasA = pack2(ba, ba), biasB = pack2(bb, bb);

    float mA = 0.f, mB = 0.f;        // relu >= 0 -> 0-init exact
    #pragma unroll
    for (int q = 0; q < NPTS / 4; q++) {       // point-quads via LDS.128
        uint64_t x01[DIN], x23[DIN];
        #pragma unroll
        for (int d = 0; d < DIN; d++) {
            float4 t = *reinterpret_cast<const float4*>(&s_pts[warp][d][4 * q]);
            x01[d] = pack2(t.x, t.y); x23[d] = pack2(t.z, t.w);
        }
        uint64_t sA0 = biasA, sB0 = biasB, sA1 = biasA, sB1 = biasB;
        #pragma unroll
        for (int d = 0; d < DIN; d++) {
            sA0 = fma2(x01[d], wA[d], sA0); sB0 = fma2(x01[d], wB[d], sB0);
            sA1 = fma2(x23[d], wA[d], sA1); sB1 = fma2(x23[d], wB[d], sB1);
        }
        float lo, hi;
        unpack2(sA0, lo, hi); mA = fmaxf(mA, fmaxf(lo, hi));
        unpack2(sA1, lo, hi); mA = fmaxf(mA, fmaxf(lo, hi));
        unpack2(sB0, lo, hi); mB = fmaxf(mB, fmaxf(lo, hi));
        unpack2(sB1, lo, hi); mB = fmaxf(mB, fmaxf(lo, hi));
    }

    const int y = __ldg(&coords[(size_t)(batch * NPILLARS + p) * 2 + 0]);
    const int x = __ldg(&coords[(size_t)(batch * NPILLARS + p) * 2 + 1]);
    const int cell = batch * HW + y * BEV_W + x;
    if (lane == 0) g_flag[cell] = 1;
    float* a = g_acc + (size_t)cell * CCH;
    atomicAdd(a + lane, mA);                 // 64 contiguous floats -> coalesced REDG
    atomicAdd(a + lane + 32, mB);
}

// ---------------- expand one batch slice (64MB dense store) ----------------
__device__ __forceinline__ void do_expand(float* __restrict__ out, int eb, int expBlk) {
    float4* dst = (float4*)(out + (size_t)eb * CCH * HW);
    const unsigned char* fl = g_flag + eb * HW;
    const float* ab = g_acc + (size_t)eb * HW * CCH;
    #pragma unroll
    for (int k = 0; k < 4; k++) {
        const int i = (expBlk + k * NEXP) * 256 + threadIdx.x;   // [0, 4,194,304)
        const int c = i >> 16;                 // 65536 float4 per channel plane
        const int rem = i & 65535;
        const int cell = ((rem >> 7) << 9) | ((rem & 127) << 2); // y*512 + 4*xq
        const uchar4 f4 = *(const uchar4*)(fl + cell);
        float4 val = make_float4(0.f, 0.f, 0.f, 0.f);
        if (f4.x | f4.y | f4.z | f4.w) {
            if (f4.x) val.x = ab[(size_t)(cell + 0) * CCH + c];
            if (f4.y) val.y = ab[(size_t)(cell + 1) * CCH + c];
            if (f4.z) val.z = ab[(size_t)(cell + 2) * CCH + c];
            if (f4.w) val.w = ab[(size_t)(cell + 3) * CCH + c];
        }
        dst[i] = val;
    }
}

// ---------------- fused pipeline stage ----------------
__global__ __launch_bounds__(256) void stage_kernel(
    const float* __restrict__ pillars, const int* __restrict__ coords,
    const float* __restrict__ w, const float* __restrict__ bias,
    float* __restrict__ out, int pfn_batch, int exp_batch)
{
    const int nPfn = (pfn_batch >= 0) ? NPFN : 0;
    if ((int)blockIdx.x < nPfn)
        do_pfn(pillars, coords, w, bias, pfn_batch, blockIdx.x);
    else
        do_expand(out, exp_batch, blockIdx.x - nPfn);
}

extern "C" void kernel_launch(void* const* d_in, const int* in_sizes, int n_in,
                              void* d_out, int out_size) {
    const float* pillars = (const float*)d_in[0];
    const int*   coords  = (const int*)d_in[1];
    const float* pfn_w   = (const float*)d_in[2];
    const float* pfn_b   = (const float*)d_in[3];
    float* out = (float*)d_out;

    prep_kernel<<<256 + 4 * NPILLARS / PPB, 256>>>(coords);             // 6256 blocks
    stage_kernel<<<NPFN, 256>>>(pillars, coords, pfn_w, pfn_b, out, 0, -1);
    stage_kernel<<<NPFN + NEXP, 256>>>(pillars, coords, pfn_w, pfn_b, out, 1, 0);
    stage_kernel<<<NPFN + NEXP, 256>>>(pillars, coords, pfn_w, pfn_b, out, 2, 1);
    stage_kernel<<<NPFN + NEXP, 256>>>(pillars, coords, pfn_w, pfn_b, out, 3, 2);
    stage_kernel<<<NEXP, 256>>>(pillars, coords, pfn_w, pfn_b, out, -1, 3);
}